// round 13
// baseline (speedup 1.0000x reference)
#include <cuda_runtime.h>
#include <cuda_fp16.h>
#include <cstdint>

#define NN 100000
#define NE 1200000
#define NG 256
#define HID 64
#define INC 5
#define NBLK ((NN + 255) / 256)

// -------- scratch (device globals; no allocation allowed) --------
__device__ __align__(256) __half g_xpre[NN * 8];     // dinv*x, 5 used of 8 halves
__device__ __align__(256) __half g_h1[NN * HID];     // h1pre = dinv*relu(lin1) fp16
__device__ __align__(256) int    g_degi[NN];
__device__ __align__(256) int    g_rowptr[NN];
__device__ __align__(256) int    g_cursor[NN];
__device__ __align__(256) float  g_dinv[NN];
__device__ __align__(256) int    g_csri[NE];         // src per edge, dst-grouped
__device__ __align__(256) float  g_pooled[NG * HID];
__device__ __align__(256) float  g_cnt[NG];
__device__ int g_gbase;

__device__ __forceinline__ void red4(float* p, float a, float b, float c, float d) {
    asm volatile("red.global.add.v4.f32 [%0], {%1,%2,%3,%4};"
                 :: "l"(p), "f"(a), "f"(b), "f"(c), "f"(d) : "memory");
}

// -------- init --------
__global__ void k_init() {
    int i = blockIdx.x * blockDim.x + threadIdx.x;
    if (i < NN) g_degi[i] = 0;
    if (i < NG * HID) g_pooled[i] = 0.f;
    if (i < NG) g_cnt[i] = 0.f;
    if (i == 0) g_gbase = 0;
}

// -------- degree: 4 edges/thread, int4 loads --------
__global__ void k_degi4(const int* __restrict__ dst) {
    int t = blockIdx.x * blockDim.x + threadIdx.x;
    if (t >= NE / 4) return;
    int4 d = __ldg((const int4*)dst + t);
    atomicAdd(&g_degi[d.x], 1);
    atomicAdd(&g_degi[d.y], 1);
    atomicAdd(&g_degi[d.z], 1);
    atomicAdd(&g_degi[d.w], 1);
}

// -------- single-pass scan (block scan + atomic base) + node prep --------
__global__ void k_scan(const float* __restrict__ x, const int* __restrict__ batch) {
    __shared__ int sh[256];
    __shared__ int sbase;
    int i = blockIdx.x * 256 + threadIdx.x;
    int v = (i < NN) ? g_degi[i] : 0;
    sh[threadIdx.x] = v;
    __syncthreads();
    for (int off = 1; off < 256; off <<= 1) {
        int t = (threadIdx.x >= off) ? sh[threadIdx.x - off] : 0;
        __syncthreads();
        sh[threadIdx.x] += t;
        __syncthreads();
    }
    if (threadIdx.x == 255) sbase = atomicAdd(&g_gbase, sh[255]);
    __syncthreads();
    if (i >= NN) return;
    int r = sbase + sh[threadIdx.x] - v;
    g_rowptr[i] = r;
    g_cursor[i] = r;
    float di = rsqrtf((float)v + 1.0f);       // +1 = self-loop
    g_dinv[i] = di;
    const float* xr = x + i * INC;
    __half2 h0 = __floats2half2_rn(di * __ldg(xr + 0), di * __ldg(xr + 1));
    __half2 h1 = __floats2half2_rn(di * __ldg(xr + 2), di * __ldg(xr + 3));
    __half2 h2 = __floats2half2_rn(di * __ldg(xr + 4), 0.f);
    uint4 u;
    u.x = *(unsigned*)&h0; u.y = *(unsigned*)&h1;
    u.z = *(unsigned*)&h2; u.w = 0u;
    *(uint4*)(g_xpre + i * 8) = u;
    atomicAdd(&g_cnt[__ldg(batch + i)], 1.0f);
}

// -------- scatter: 4 edges/thread, int4 loads, 4 atomics in flight --------
__global__ void k_scatter4(const int* __restrict__ src, const int* __restrict__ dst) {
    int t = blockIdx.x * blockDim.x + threadIdx.x;
    if (t >= NE / 4) return;
    int4 s = __ldg((const int4*)src + t);
    int4 d = __ldg((const int4*)dst + t);
    int sl0 = atomicAdd(&g_cursor[d.x], 1);
    int sl1 = atomicAdd(&g_cursor[d.y], 1);
    int sl2 = atomicAdd(&g_cursor[d.z], 1);
    int sl3 = atomicAdd(&g_cursor[d.w], 1);
    g_csri[sl0] = s.x;
    g_csri[sl1] = s.y;
    g_csri[sl2] = s.z;
    g_csri[sl3] = s.w;
}

__device__ __forceinline__ void acc5(uint4 u, float a[5]) {
    float2 f0 = __half22float2(*(__half2*)&u.x);
    float2 f1 = __half22float2(*(__half2*)&u.y);
    float2 f2 = __half22float2(*(__half2*)&u.z);
    a[0] += f0.x; a[1] += f0.y; a[2] += f1.x; a[3] += f1.y; a[4] += f2.x;
}

// -------- layer 1 fused: agg(x) -> W1 GEMV -> relu -> fp16 h1pre ----------
// One thread per node. W1/b1 in smem (broadcast LDS).
__global__ void __launch_bounds__(256) k_l1(const float* __restrict__ W1,
                                            const float* __restrict__ b1) {
    __shared__ float sW[INC * HID];
    __shared__ float sb[HID];
    for (int i = threadIdx.x; i < INC * HID; i += 256) sW[i] = W1[i];
    for (int i = threadIdx.x; i < HID; i += 256) sb[i] = b1[i];
    __syncthreads();
    int n = blockIdx.x * 256 + threadIdx.x;
    if (n >= NN) return;
    int i = g_rowptr[n];
    int end = i + g_degi[n];
    float a[5] = {0.f, 0.f, 0.f, 0.f, 0.f};
    for (; i + 4 <= end; i += 4) {
        int4 s = make_int4(__ldg(g_csri + i), __ldg(g_csri + i + 1),
                           __ldg(g_csri + i + 2), __ldg(g_csri + i + 3));
        acc5(__ldg((const uint4*)(g_xpre + s.x * 8)), a);
        acc5(__ldg((const uint4*)(g_xpre + s.y * 8)), a);
        acc5(__ldg((const uint4*)(g_xpre + s.z * 8)), a);
        acc5(__ldg((const uint4*)(g_xpre + s.w * 8)), a);
    }
    for (; i < end; i++)
        acc5(__ldg((const uint4*)(g_xpre + __ldg(g_csri + i) * 8)), a);
    acc5(*(const uint4*)(g_xpre + n * 8), a);   // self term
    float di = g_dinv[n];
#pragma unroll
    for (int k = 0; k < INC; k++) a[k] *= di;   // aggX
    // GEMV + relu + dinv premul + fp16 pack, 8 channels at a time
#pragma unroll
    for (int c8 = 0; c8 < 8; c8++) {
        float4 r0 = *(const float4*)(sb + c8 * 8);
        float4 r1 = *(const float4*)(sb + c8 * 8 + 4);
#pragma unroll
        for (int k = 0; k < INC; k++) {
            float4 w0 = *(const float4*)(sW + k * HID + c8 * 8);
            float4 w1 = *(const float4*)(sW + k * HID + c8 * 8 + 4);
            r0.x = fmaf(a[k], w0.x, r0.x); r0.y = fmaf(a[k], w0.y, r0.y);
            r0.z = fmaf(a[k], w0.z, r0.z); r0.w = fmaf(a[k], w0.w, r0.w);
            r1.x = fmaf(a[k], w1.x, r1.x); r1.y = fmaf(a[k], w1.y, r1.y);
            r1.z = fmaf(a[k], w1.z, r1.z); r1.w = fmaf(a[k], w1.w, r1.w);
        }
        __half2 p0 = __floats2half2_rn(di * fmaxf(r0.x, 0.f), di * fmaxf(r0.y, 0.f));
        __half2 p1 = __floats2half2_rn(di * fmaxf(r0.z, 0.f), di * fmaxf(r0.w, 0.f));
        __half2 p2 = __floats2half2_rn(di * fmaxf(r1.x, 0.f), di * fmaxf(r1.y, 0.f));
        __half2 p3 = __floats2half2_rn(di * fmaxf(r1.z, 0.f), di * fmaxf(r1.w, 0.f));
        uint4 u;
        u.x = *(unsigned*)&p0; u.y = *(unsigned*)&p1;
        u.z = *(unsigned*)&p2; u.w = *(unsigned*)&p3;
        *(uint4*)(g_h1 + (size_t)n * HID + c8 * 8) = u;
    }
}

__device__ __forceinline__ void acc8(uint4 u, float a[8]) {
    float2 f0 = __half22float2(*(__half2*)&u.x);
    float2 f1 = __half22float2(*(__half2*)&u.y);
    float2 f2 = __half22float2(*(__half2*)&u.z);
    float2 f3 = __half22float2(*(__half2*)&u.w);
    a[0] += f0.x; a[1] += f0.y; a[2] += f1.x; a[3] += f1.y;
    a[4] += f2.x; a[5] += f2.y; a[6] += f3.x; a[7] += f3.y;
}

// -------- layer 2 fused: agg(h1) -> smem -> W2 GEMV -> relu -> pool RED ---
// 64 nodes/block, 512 threads: 8 lanes/node aggregate, then 8 ch-groups/node GEMV.
__global__ void __launch_bounds__(512) k_l2(const float* __restrict__ W2,
                                            const float* __restrict__ b2,
                                            const int* __restrict__ batch) {
    __shared__ float Ws[HID * HID];        // 16 KB
    __shared__ float sA[64 * HID];         // 16 KB aggregated hidden
    for (int i = threadIdx.x; i < HID * HID; i += 512) Ws[i] = W2[i];
    int nl = threadIdx.x >> 3;             // 0..63 node slot
    int l  = (threadIdx.x & 7) * 8;        // channel base
    int n = blockIdx.x * 64 + nl;
    if (n < NN) {
        int i = g_rowptr[n];
        int end = i + g_degi[n];
        float a[8] = {0.f, 0.f, 0.f, 0.f, 0.f, 0.f, 0.f, 0.f};
        for (; i + 4 <= end; i += 4) {
            int s0 = __ldg(g_csri + i);
            int s1 = __ldg(g_csri + i + 1);
            int s2 = __ldg(g_csri + i + 2);
            int s3 = __ldg(g_csri + i + 3);
            acc8(__ldg((const uint4*)(g_h1 + (size_t)s0 * HID + l)), a);
            acc8(__ldg((const uint4*)(g_h1 + (size_t)s1 * HID + l)), a);
            acc8(__ldg((const uint4*)(g_h1 + (size_t)s2 * HID + l)), a);
            acc8(__ldg((const uint4*)(g_h1 + (size_t)s3 * HID + l)), a);
        }
        for (; i < end; i++)
            acc8(__ldg((const uint4*)(g_h1 + (size_t)__ldg(g_csri + i) * HID + l)), a);
        acc8(*(const uint4*)(g_h1 + (size_t)n * HID + l), a);   // self
        float di = g_dinv[n];
        float* o = sA + nl * HID + l;
        *(float4*)o       = make_float4(di * a[0], di * a[1], di * a[2], di * a[3]);
        *(float4*)(o + 4) = make_float4(di * a[4], di * a[5], di * a[6], di * a[7]);
    }
    __syncthreads();
    if (n >= NN) return;
    // GEMV: node nl, output channels l..l+7
    float4 c0 = __ldg((const float4*)(b2 + l));
    float4 c1 = __ldg((const float4*)(b2 + l + 4));
    const float* hr = sA + nl * HID;
#pragma unroll 4
    for (int k = 0; k < HID; k++) {
        float hv = hr[k];
        float4 w0 = *(const float4*)(Ws + k * HID + l);
        float4 w1 = *(const float4*)(Ws + k * HID + l + 4);
        c0.x = fmaf(hv, w0.x, c0.x); c0.y = fmaf(hv, w0.y, c0.y);
        c0.z = fmaf(hv, w0.z, c0.z); c0.w = fmaf(hv, w0.w, c0.w);
        c1.x = fmaf(hv, w1.x, c1.x); c1.y = fmaf(hv, w1.y, c1.y);
        c1.z = fmaf(hv, w1.z, c1.z); c1.w = fmaf(hv, w1.w, c1.w);
    }
    int g = __ldg(batch + n);
    red4(&g_pooled[g * HID + l],
         fmaxf(c0.x, 0.f), fmaxf(c0.y, 0.f), fmaxf(c0.z, 0.f), fmaxf(c0.w, 0.f));
    red4(&g_pooled[g * HID + l + 4],
         fmaxf(c1.x, 0.f), fmaxf(c1.y, 0.f), fmaxf(c1.z, 0.f), fmaxf(c1.w, 0.f));
}

// -------- final: out[g][o] = (pooled[g]@Wfc)[o]/cnt[g] + bfc[o] -----------
__global__ void k_final(const float* __restrict__ Wfc,
                        const float* __restrict__ bfc,
                        float* __restrict__ out) {
    int t = threadIdx.x;                // 512 threads: (g, o)
    int g = t >> 1, o = t & 1;
    float acc = 0.f;
#pragma unroll
    for (int c = 0; c < HID; c++)
        acc += g_pooled[g * HID + c] * __ldg(Wfc + c * 2 + o);
    float cnt = fmaxf(g_cnt[g], 1.0f);
    out[g * 2 + o] = acc / cnt + __ldg(bfc + o);
}

extern "C" void kernel_launch(void* const* d_in, const int* in_sizes, int n_in,
                              void* d_out, int out_size) {
    const float* x     = (const float*)d_in[0];
    const int*   ei    = (const int*)d_in[1];     // int32 (JAX x64 disabled)
    const int*   batch = (const int*)d_in[2];
    const float* W1    = (const float*)d_in[3];
    const float* b1    = (const float*)d_in[4];
    const float* W2    = (const float*)d_in[5];
    const float* b2    = (const float*)d_in[6];
    const float* Wfc   = (const float*)d_in[7];
    const float* bfc   = (const float*)d_in[8];
    float*       out   = (float*)d_out;

    const int* src = ei;
    const int* dst = ei + NE;

    const int T = 256;
    k_init<<<(NN + T - 1) / T, T>>>();
    k_degi4<<<(NE / 4 + T - 1) / T, T>>>(dst);
    k_scan<<<NBLK, 256>>>(x, batch);
    k_scatter4<<<(NE / 4 + T - 1) / T, T>>>(src, dst);
    k_l1<<<(NN + 255) / 256, 256>>>(W1, b1);
    k_l2<<<(NN + 63) / 64, 512>>>(W2, b2, batch);
    k_final<<<1, 512>>>(Wfc, bfc, out);
}

// round 15
// speedup vs baseline: 1.1913x; 1.1913x over previous
#include <cuda_runtime.h>
#include <cuda_fp16.h>
#include <cstdint>

#define NN 100000
#define NE 1200000
#define NG 256
#define HID 64
#define INC 5
#define NBLK ((NN + 255) / 256)

// -------- scratch (device globals; no allocation allowed) --------
__device__ __align__(256) __half g_xpre[NN * 8];     // dinv*x, 5 used of 8 halves
__device__ __align__(256) float  g_aggx[NN * 8];     // layer-1 aggregated input (5 used)
__device__ __align__(256) __half g_h1[NN * HID];     // h1pre = dinv*relu(lin1) fp16
__device__ __align__(256) float  g_aggh[NN * HID];   // layer-2 aggregated hidden
__device__ __align__(256) int    g_degi[NN];
__device__ __align__(256) int    g_rowptr[NN];
__device__ __align__(256) int    g_wslot[NE];        // within-node slot per edge
__device__ __align__(256) float  g_dinv[NN];
__device__ __align__(256) int    g_csri[NE];         // src per edge, dst-grouped
__device__ __align__(256) float  g_pooled[NG * HID];
__device__ __align__(256) float  g_cnt[NG];
__device__ int g_gbase;

__device__ __forceinline__ void red4(float* p, float a, float b, float c, float d) {
    asm volatile("red.global.add.v4.f32 [%0], {%1,%2,%3,%4};"
                 :: "l"(p), "f"(a), "f"(b), "f"(c), "f"(d) : "memory");
}

// -------- init --------
__global__ void k_init() {
    int i = blockIdx.x * blockDim.x + threadIdx.x;
    if (i < NN) g_degi[i] = 0;
    if (i < NG * HID) g_pooled[i] = 0.f;
    if (i < NG) g_cnt[i] = 0.f;
    if (i == 0) g_gbase = 0;
}

// -------- degree + within-node slot capture (4 edges/thread) --------
__global__ void k_degi4(const int* __restrict__ dst) {
    int t = blockIdx.x * blockDim.x + threadIdx.x;
    if (t >= NE / 4) return;
    int4 d = __ldg((const int4*)dst + t);
    int4 w;
    w.x = atomicAdd(&g_degi[d.x], 1);
    w.y = atomicAdd(&g_degi[d.y], 1);
    w.z = atomicAdd(&g_degi[d.z], 1);
    w.w = atomicAdd(&g_degi[d.w], 1);
    ((int4*)g_wslot)[t] = w;
}

// -------- single-pass scan (block scan + atomic base) + node prep --------
__global__ void k_scan(const float* __restrict__ x, const int* __restrict__ batch) {
    __shared__ int sh[256];
    __shared__ int sbase;
    int i = blockIdx.x * 256 + threadIdx.x;
    int v = (i < NN) ? g_degi[i] : 0;
    sh[threadIdx.x] = v;
    __syncthreads();
    for (int off = 1; off < 256; off <<= 1) {
        int t = (threadIdx.x >= off) ? sh[threadIdx.x - off] : 0;
        __syncthreads();
        sh[threadIdx.x] += t;
        __syncthreads();
    }
    if (threadIdx.x == 255) sbase = atomicAdd(&g_gbase, sh[255]);
    __syncthreads();
    if (i >= NN) return;
    g_rowptr[i] = sbase + sh[threadIdx.x] - v;    // exclusive offset
    float di = rsqrtf((float)v + 1.0f);           // +1 = self-loop
    g_dinv[i] = di;
    const float* xr = x + i * INC;
    __half2 h0 = __floats2half2_rn(di * __ldg(xr + 0), di * __ldg(xr + 1));
    __half2 h1 = __floats2half2_rn(di * __ldg(xr + 2), di * __ldg(xr + 3));
    __half2 h2 = __floats2half2_rn(di * __ldg(xr + 4), 0.f);
    uint4 u;
    u.x = *(unsigned*)&h0; u.y = *(unsigned*)&h1;
    u.z = *(unsigned*)&h2; u.w = 0u;
    *(uint4*)(g_xpre + i * 8) = u;
    atomicAdd(&g_cnt[__ldg(batch + i)], 1.0f);
}

// -------- scatter: ATOMIC-FREE. slot = rowptr[d] + wslot[e] --------
__global__ void k_scatter4(const int* __restrict__ src, const int* __restrict__ dst) {
    int t = blockIdx.x * blockDim.x + threadIdx.x;
    if (t >= NE / 4) return;
    int4 s = __ldg((const int4*)src + t);
    int4 d = __ldg((const int4*)dst + t);
    int4 w = ((const int4*)g_wslot)[t];
    g_csri[__ldg(g_rowptr + d.x) + w.x] = s.x;
    g_csri[__ldg(g_rowptr + d.y) + w.y] = s.y;
    g_csri[__ldg(g_rowptr + d.z) + w.z] = s.z;
    g_csri[__ldg(g_rowptr + d.w) + w.w] = s.w;
}

__device__ __forceinline__ void acc5(uint4 u, float a[5]) {
    float2 f0 = __half22float2(*(__half2*)&u.x);
    float2 f1 = __half22float2(*(__half2*)&u.y);
    float2 f2 = __half22float2(*(__half2*)&u.z);
    a[0] += f0.x; a[1] += f0.y; a[2] += f1.x; a[3] += f1.y; a[4] += f2.x;
}

// -------- layer-1 aggregation: aggX = dinv*(sum xpre[src] + xpre[n]) ------
__global__ void k_aggx() {
    int n = blockIdx.x * blockDim.x + threadIdx.x;
    if (n >= NN) return;
    int i = g_rowptr[n];
    int end = i + g_degi[n];
    float a[5] = {0.f, 0.f, 0.f, 0.f, 0.f};
    for (; i + 2 <= end; i += 2) {
        int s0 = __ldg(g_csri + i);
        int s1 = __ldg(g_csri + i + 1);
        acc5(__ldg((const uint4*)(g_xpre + s0 * 8)), a);
        acc5(__ldg((const uint4*)(g_xpre + s1 * 8)), a);
    }
    if (i < end)
        acc5(__ldg((const uint4*)(g_xpre + __ldg(g_csri + i) * 8)), a);
    acc5(*(const uint4*)(g_xpre + n * 8), a);   // self term
    float di = g_dinv[n];
    float* o = g_aggx + n * 8;
    *(float4*)o = make_float4(di * a[0], di * a[1], di * a[2], di * a[3]);
    o[4] = di * a[4];
}

// -------- lin1: h1pre = dinv * relu(aggX @ W1 + b1) -> fp16; 8 ch/thread --
__global__ void k_lin1(const float* __restrict__ W1, const float* __restrict__ b1) {
    int idx = blockIdx.x * blockDim.x + threadIdx.x;   // NN*8 threads
    if (idx >= NN * 8) return;
    int n = idx >> 3, c8 = (idx & 7) * 8;
    float xr[INC];
#pragma unroll
    for (int k = 0; k < INC; k++) xr[k] = __ldg(g_aggx + n * 8 + k);
    float4 a0 = __ldg((const float4*)(b1 + c8));
    float4 a1 = __ldg((const float4*)(b1 + c8 + 4));
#pragma unroll
    for (int k = 0; k < INC; k++) {
        float4 w0 = __ldg((const float4*)(W1 + k * HID + c8));
        float4 w1 = __ldg((const float4*)(W1 + k * HID + c8 + 4));
        a0.x = fmaf(xr[k], w0.x, a0.x); a0.y = fmaf(xr[k], w0.y, a0.y);
        a0.z = fmaf(xr[k], w0.z, a0.z); a0.w = fmaf(xr[k], w0.w, a0.w);
        a1.x = fmaf(xr[k], w1.x, a1.x); a1.y = fmaf(xr[k], w1.y, a1.y);
        a1.z = fmaf(xr[k], w1.z, a1.z); a1.w = fmaf(xr[k], w1.w, a1.w);
    }
    float di = g_dinv[n];
    __half2 p0 = __floats2half2_rn(di * fmaxf(a0.x, 0.f), di * fmaxf(a0.y, 0.f));
    __half2 p1 = __floats2half2_rn(di * fmaxf(a0.z, 0.f), di * fmaxf(a0.w, 0.f));
    __half2 p2 = __floats2half2_rn(di * fmaxf(a1.x, 0.f), di * fmaxf(a1.y, 0.f));
    __half2 p3 = __floats2half2_rn(di * fmaxf(a1.z, 0.f), di * fmaxf(a1.w, 0.f));
    uint4 u;
    u.x = *(unsigned*)&p0; u.y = *(unsigned*)&p1;
    u.z = *(unsigned*)&p2; u.w = *(unsigned*)&p3;
    *(uint4*)(g_h1 + (size_t)n * HID + c8) = u;
}

__device__ __forceinline__ void acc8(uint4 u, float a[8]) {
    float2 f0 = __half22float2(*(__half2*)&u.x);
    float2 f1 = __half22float2(*(__half2*)&u.y);
    float2 f2 = __half22float2(*(__half2*)&u.z);
    float2 f3 = __half22float2(*(__half2*)&u.w);
    a[0] += f0.x; a[1] += f0.y; a[2] += f1.x; a[3] += f1.y;
    a[4] += f2.x; a[5] += f2.y; a[6] += f3.x; a[7] += f3.y;
}

// -------- layer-2 aggregation: aggH = dinv*(sum h1pre[src] + h1pre[n]) ----
// 8 lanes/node, each lane covers 8 fp16 channels (16B load per edge).
__global__ void k_aggh() {
    int t = blockIdx.x * blockDim.x + threadIdx.x;   // NN*8 threads
    int n = t >> 3;
    if (n >= NN) return;
    int l = (t & 7) * 8;
    int i = g_rowptr[n];
    int end = i + g_degi[n];
    float a[8] = {0.f, 0.f, 0.f, 0.f, 0.f, 0.f, 0.f, 0.f};
    for (; i + 2 <= end; i += 2) {
        int s0 = __ldg(g_csri + i);
        int s1 = __ldg(g_csri + i + 1);
        acc8(__ldg((const uint4*)(g_h1 + (size_t)s0 * HID + l)), a);
        acc8(__ldg((const uint4*)(g_h1 + (size_t)s1 * HID + l)), a);
    }
    if (i < end)
        acc8(__ldg((const uint4*)(g_h1 + (size_t)__ldg(g_csri + i) * HID + l)), a);
    acc8(*(const uint4*)(g_h1 + (size_t)n * HID + l), a);   // self
    float di = g_dinv[n];
    float* o = g_aggh + (size_t)n * HID + l;
    *(float4*)o       = make_float4(di * a[0], di * a[1], di * a[2], di * a[3]);
    *(float4*)(o + 4) = make_float4(di * a[4], di * a[5], di * a[6], di * a[7]);
}

// -------- lin2 fused with relu + mean-pool RED (no h2 buffer) -------------
__global__ void __launch_bounds__(128) k_lin2pool(const float* __restrict__ W2,
                                                  const float* __restrict__ b2,
                                                  const int* __restrict__ batch) {
    __shared__ float Ws[HID * HID];
    for (int i = threadIdx.x; i < HID * HID; i += 128) Ws[i] = W2[i];
    __syncthreads();
    int nb = blockIdx.x * 64;
    int ng = threadIdx.x >> 3;
    int c8 = (threadIdx.x & 7) * 8;
    int n0 = nb + ng;
    const float* h0 = g_aggh + (size_t)min(n0,      NN - 1) * HID;
    const float* h1 = g_aggh + (size_t)min(n0 + 16, NN - 1) * HID;
    const float* h2 = g_aggh + (size_t)min(n0 + 32, NN - 1) * HID;
    const float* h3 = g_aggh + (size_t)min(n0 + 48, NN - 1) * HID;
    float a[4][8];
#pragma unroll
    for (int j = 0; j < 4; j++)
#pragma unroll
        for (int c = 0; c < 8; c++) a[j][c] = 0.f;
#pragma unroll 4
    for (int k = 0; k < HID; k++) {
        float4 w0 = *(const float4*)(Ws + k * HID + c8);
        float4 w1 = *(const float4*)(Ws + k * HID + c8 + 4);
        float hv[4] = {__ldg(h0 + k), __ldg(h1 + k), __ldg(h2 + k), __ldg(h3 + k)};
#pragma unroll
        for (int j = 0; j < 4; j++) {
            a[j][0] = fmaf(hv[j], w0.x, a[j][0]); a[j][1] = fmaf(hv[j], w0.y, a[j][1]);
            a[j][2] = fmaf(hv[j], w0.z, a[j][2]); a[j][3] = fmaf(hv[j], w0.w, a[j][3]);
            a[j][4] = fmaf(hv[j], w1.x, a[j][4]); a[j][5] = fmaf(hv[j], w1.y, a[j][5]);
            a[j][6] = fmaf(hv[j], w1.z, a[j][6]); a[j][7] = fmaf(hv[j], w1.w, a[j][7]);
        }
    }
    float4 bb0 = __ldg((const float4*)(b2 + c8));
    float4 bb1 = __ldg((const float4*)(b2 + c8 + 4));
#pragma unroll
    for (int j = 0; j < 4; j++) {
        int n = n0 + 16 * j;
        if (n < NN) {
            int g = __ldg(batch + n);
            float r0 = fmaxf(a[j][0] + bb0.x, 0.f);
            float r1 = fmaxf(a[j][1] + bb0.y, 0.f);
            float r2 = fmaxf(a[j][2] + bb0.z, 0.f);
            float r3 = fmaxf(a[j][3] + bb0.w, 0.f);
            float r4 = fmaxf(a[j][4] + bb1.x, 0.f);
            float r5 = fmaxf(a[j][5] + bb1.y, 0.f);
            float r6 = fmaxf(a[j][6] + bb1.z, 0.f);
            float r7 = fmaxf(a[j][7] + bb1.w, 0.f);
            red4(&g_pooled[g * HID + c8],     r0, r1, r2, r3);
            red4(&g_pooled[g * HID + c8 + 4], r4, r5, r6, r7);
        }
    }
}

// -------- final: out[g][o] = (pooled[g]@Wfc)[o]/cnt[g] + bfc[o] -----------
__global__ void k_final(const float* __restrict__ Wfc,
                        const float* __restrict__ bfc,
                        float* __restrict__ out) {
    int t = threadIdx.x;                // 512 threads: (g, o)
    int g = t >> 1, o = t & 1;
    float acc = 0.f;
#pragma unroll
    for (int c = 0; c < HID; c++)
        acc += g_pooled[g * HID + c] * __ldg(Wfc + c * 2 + o);
    float cnt = fmaxf(g_cnt[g], 1.0f);
    out[g * 2 + o] = acc / cnt + __ldg(bfc + o);
}

extern "C" void kernel_launch(void* const* d_in, const int* in_sizes, int n_in,
                              void* d_out, int out_size) {
    const float* x     = (const float*)d_in[0];
    const int*   ei    = (const int*)d_in[1];     // int32 (JAX x64 disabled)
    const int*   batch = (const int*)d_in[2];
    const float* W1    = (const float*)d_in[3];
    const float* b1    = (const float*)d_in[4];
    const float* W2    = (const float*)d_in[5];
    const float* b2    = (const float*)d_in[6];
    const float* Wfc   = (const float*)d_in[7];
    const float* bfc   = (const float*)d_in[8];
    float*       out   = (float*)d_out;

    const int* src = ei;
    const int* dst = ei + NE;

    const int T = 256;
    k_init<<<(NN + T - 1) / T, T>>>();
    k_degi4<<<(NE / 4 + T - 1) / T, T>>>(dst);
    k_scan<<<NBLK, 256>>>(x, batch);
    k_scatter4<<<(NE / 4 + T - 1) / T, T>>>(src, dst);
    k_aggx<<<(NN + T - 1) / T, T>>>();
    k_lin1<<<(NN * 8 + T - 1) / T, T>>>(W1, b1);
    k_aggh<<<(NN * 8 + T - 1) / T, T>>>();
    k_lin2pool<<<(NN + 63) / 64, 128>>>(W2, b2, batch);
    k_final<<<1, 512>>>(Wfc, bfc, out);
}